// round 9
// baseline (speedup 1.0000x reference)
#include <cuda_runtime.h>
#include <cuda_fp16.h>
#include <mma.h>
#include <stdint.h>

using namespace nvcuda;

#define N_NODES_MAX 100000
#define N_PAD       100096            // multiple of 128
#define E_MAX       1600000
#define CH          128

// ---------------- scratch (static device globals; zero-initialized) ----------
__device__ __align__(16) int     g_cnt[N_NODES_MAX];   // zero at start of each run
__device__ __align__(16) int     g_rowstart[N_NODES_MAX];
__device__ __align__(16) int     g_cursor[N_NODES_MAX];
__device__ __align__(16) uint2   g_csr[E_MAX];         // {src, weight bits}
__device__ __align__(16) float   g_dinv[N_NODES_MAX];
__device__               int     g_total;
__device__ __align__(16) __half2 g_xh[(size_t)N_NODES_MAX * 64];  // x in fp16
__device__ __align__(16) __half2 g_aggh[(size_t)N_PAD * 64];      // agg in fp16
__device__ __align__(16) __half2 g_Wh[CH * CH / 2];               // W in fp16

// ---------------- kernel 1: convert x,W to fp16 + count in-degree -------------
__global__ void k_prep_count(const float2* __restrict__ x2,
                             const float2* __restrict__ W2,
                             const int* __restrict__ ei, int E, int n) {
    int i = blockIdx.x * blockDim.x + threadIdx.x;
    int conv = n * 64;
    if (i < conv) g_xh[i] = __float22half2_rn(x2[i]);
    if (i < CH * CH / 2) g_Wh[i] = __float22half2_rn(W2[i]);
    if (i < E) {
        unsigned dst = (unsigned)ei[E + i];
        if (dst < (unsigned)n) atomicAdd(&g_cnt[dst], 1);
    }
    if (i == 0) g_total = 0;
}

// ---------------- kernel 2: allocate CSR ranges (warp-aggregated atomic) ------
__global__ void k_alloc(int n) {
    int i    = blockIdx.x * blockDim.x + threadIdx.x;
    int lane = threadIdx.x & 31;
    int c = (i < n) ? g_cnt[i] : 0;

    int pre = c;
    #pragma unroll
    for (int off = 1; off < 32; off <<= 1) {
        int t = __shfl_up_sync(0xffffffffu, pre, off);
        if (lane >= off) pre += t;
    }
    int base = 0;
    if (lane == 31) base = atomicAdd(&g_total, pre);
    base = __shfl_sync(0xffffffffu, base, 31);
    if (i < n) {
        int rs = base + pre - c;
        g_rowstart[i] = rs;
        g_cursor[i]   = rs;
        g_dinv[i]     = rsqrtf(1.0f + (float)c);   // +1 self loop
    }
}

// ---------------- kernel 3: CSR fill with precomputed weights ------------------
__global__ void k_fill(const int* __restrict__ ei, int E, int n) {
    int e = blockIdx.x * blockDim.x + threadIdx.x;
    if (e < E) {
        unsigned src = (unsigned)ei[e];
        unsigned dst = (unsigned)ei[E + e];
        if (src < (unsigned)n && dst < (unsigned)n) {
            int pos = atomicAdd(&g_cursor[dst], 1);
            float w = g_dinv[src] * g_dinv[dst];
            if ((unsigned)pos < (unsigned)E_MAX)
                g_csr[pos] = make_uint2(src, __float_as_uint(w));
        }
    }
}

// ---------------- kernel 4: gather-aggregate (warp per node, dual-edge) -------
// lanes 0-15 process edge j, lanes 16-31 edge j+1; each lane covers 8 channels.
__global__ void __launch_bounds__(256)
k_aggregate(int n) {
    const unsigned FULL = 0xffffffffu;
    int node = (blockIdx.x * blockDim.x + threadIdx.x) >> 5;
    int lane = threadIdx.x & 31;
    if (node >= n) return;

    const int half = lane >> 4;       // 0 or 1
    const int lsub = lane & 15;       // channel-group index (16 B each)

    // self-loop seed (half 0 carries it; half 1 starts at zero)
    float di = g_dinv[node];
    float ws = (half == 0) ? di * di : 0.0f;
    uint4 sv = ((const uint4*)(g_xh + (size_t)node * 64))[lsub];
    float2 s0 = __half22float2(*(__half2*)&sv.x);
    float2 s1 = __half22float2(*(__half2*)&sv.y);
    float2 s2 = __half22float2(*(__half2*)&sv.z);
    float2 s3 = __half22float2(*(__half2*)&sv.w);
    float acc[8] = { ws * s0.x, ws * s0.y, ws * s1.x, ws * s1.y,
                     ws * s2.x, ws * s2.y, ws * s3.x, ws * s3.y };

    int start = g_rowstart[node];
    int end   = g_cursor[node];       // == rowstart + deg after fill
    int p0 = start;

    // full 32-edge groups
    for (; p0 + 32 <= end; p0 += 32) {
        uint2 rec = g_csr[p0 + lane];             // coalesced
        int   s = (int)rec.x;
        float w = __uint_as_float(rec.y);
        #pragma unroll
        for (int j = 0; j < 32; j += 2) {
            int   sj = __shfl_sync(FULL, s, j + half);
            float wj = __shfl_sync(FULL, w, j + half);
            uint4 v  = ((const uint4*)(g_xh + (size_t)sj * 64))[lsub];
            float2 a0 = __half22float2(*(__half2*)&v.x);
            float2 a1 = __half22float2(*(__half2*)&v.y);
            float2 a2 = __half22float2(*(__half2*)&v.z);
            float2 a3 = __half22float2(*(__half2*)&v.w);
            acc[0] += wj * a0.x; acc[1] += wj * a0.y;
            acc[2] += wj * a1.x; acc[3] += wj * a1.y;
            acc[4] += wj * a2.x; acc[5] += wj * a2.y;
            acc[6] += wj * a3.x; acc[7] += wj * a3.y;
        }
    }
    // tail group (0..31 edges)
    if (p0 < end) {
        int grp = end - p0;
        uint2 rec = (p0 + lane < end) ? g_csr[p0 + lane] : make_uint2(0u, 0u);
        int   s = (int)rec.x;
        float w = __uint_as_float(rec.y);
        for (int j = 0; j < grp; j += 2) {
            int idx  = j + half;
            int cidx = min(idx, grp - 1);
            int   sj = __shfl_sync(FULL, s, cidx);
            float wj = __shfl_sync(FULL, w, cidx);
            if (idx >= grp) wj = 0.0f;
            uint4 v  = ((const uint4*)(g_xh + (size_t)sj * 64))[lsub];
            float2 a0 = __half22float2(*(__half2*)&v.x);
            float2 a1 = __half22float2(*(__half2*)&v.y);
            float2 a2 = __half22float2(*(__half2*)&v.z);
            float2 a3 = __half22float2(*(__half2*)&v.w);
            acc[0] += wj * a0.x; acc[1] += wj * a0.y;
            acc[2] += wj * a1.x; acc[3] += wj * a1.y;
            acc[4] += wj * a2.x; acc[5] += wj * a2.y;
            acc[6] += wj * a3.x; acc[7] += wj * a3.y;
        }
    }

    // combine the two half-warps (channels identical across halves)
    #pragma unroll
    for (int k = 0; k < 8; k++)
        acc[k] += __shfl_down_sync(FULL, acc[k], 16);

    if (half == 0) {
        __half2 o0 = __floats2half2_rn(acc[0], acc[1]);
        __half2 o1 = __floats2half2_rn(acc[2], acc[3]);
        __half2 o2 = __floats2half2_rn(acc[4], acc[5]);
        __half2 o3 = __floats2half2_rn(acc[6], acc[7]);
        uint4 ov = make_uint4(*(unsigned*)&o0, *(unsigned*)&o1,
                              *(unsigned*)&o2, *(unsigned*)&o3);
        ((uint4*)(g_aggh + (size_t)node * 64))[lsub] = ov;
    }
}

// ---------------- kernel 5: HMMA GEMM  out = agg_h @ W_h + bias ---------------
__global__ void __launch_bounds__(256)
k_gemm(const float* __restrict__ bias, float* __restrict__ C, int M) {
    __shared__ __align__(16) __half As[128 * 136];
    __shared__ float Es[8 * 256];

    const int tid  = threadIdx.x;
    const int wid  = tid >> 5;
    const int lane = tid & 31;
    const int row0 = blockIdx.x * 128;
    const int warp_m = wid & 1;
    const int warp_n = wid >> 1;

    {
        const uint4* Ag  = (const uint4*)(g_aggh + (size_t)row0 * 64);
        uint4*       As4 = (uint4*)As;
        #pragma unroll
        for (int i = 0; i < 8; i++) {
            int idx = i * 256 + tid;
            int r   = idx >> 4;
            int c   = idx & 15;
            As4[r * 17 + c] = Ag[idx];
        }
    }
    __syncthreads();

    wmma::fragment<wmma::accumulator, 16, 16, 16, float> acc[4][2];
    #pragma unroll
    for (int mf = 0; mf < 4; mf++)
        #pragma unroll
        for (int nf = 0; nf < 2; nf++)
            wmma::fill_fragment(acc[mf][nf], 0.0f);

    const __half* Wh = (const __half*)g_Wh;

    #pragma unroll
    for (int k0 = 0; k0 < 128; k0 += 16) {
        wmma::fragment<wmma::matrix_a, 16, 16, 16, __half, wmma::row_major> af[4];
        #pragma unroll
        for (int mf = 0; mf < 4; mf++)
            wmma::load_matrix_sync(af[mf],
                As + (warp_m * 64 + mf * 16) * 136 + k0, 136);
        #pragma unroll
        for (int nf = 0; nf < 2; nf++) {
            wmma::fragment<wmma::matrix_b, 16, 16, 16, __half, wmma::row_major> bf;
            wmma::load_matrix_sync(bf, Wh + k0 * CH + warp_n * 32 + nf * 16, CH);
            #pragma unroll
            for (int mf = 0; mf < 4; mf++)
                wmma::mma_sync(acc[mf][nf], af[mf], bf, acc[mf][nf]);
        }
    }

    float* es = Es + wid * 256;
    #pragma unroll
    for (int mf = 0; mf < 4; mf++) {
        #pragma unroll
        for (int nf = 0; nf < 2; nf++) {
            wmma::store_matrix_sync(es, acc[mf][nf], 16, wmma::mem_row_major);
            __syncwarp();
            int r_in = lane >> 1;
            int c0   = (lane & 1) * 8;
            int gr   = row0 + warp_m * 64 + mf * 16 + r_in;
            int gc   = warp_n * 32 + nf * 16 + c0;
            if (gr < M) {
                float4 b0 = *(const float4*)(bias + gc);
                float4 b1 = *(const float4*)(bias + gc + 4);
                const float* p = es + r_in * 16 + c0;
                float4 o0 = make_float4(p[0] + b0.x, p[1] + b0.y,
                                        p[2] + b0.z, p[3] + b0.w);
                float4 o1 = make_float4(p[4] + b1.x, p[5] + b1.y,
                                        p[6] + b1.z, p[7] + b1.w);
                *(float4*)(C + (size_t)gr * CH + gc)     = o0;
                *(float4*)(C + (size_t)gr * CH + gc + 4) = o1;
            }
            __syncwarp();
        }
    }

    // restore invariant: g_cnt == 0 for next graph replay
    int gz = blockIdx.x * 256 + tid;
    if (gz < M) g_cnt[gz] = 0;
}

// ---------------- launch --------------------------------------------------------
extern "C" void kernel_launch(void* const* d_in, const int* in_sizes, int n_in,
                              void* d_out, int out_size) {
    const float* x    = (const float*)d_in[0];
    const int*   ei   = (const int*)d_in[1];     // int32 [2, E]
    const float* W    = (const float*)d_in[2];
    const float* bias = (const float*)d_in[3];
    float*       out  = (float*)d_out;

    int N = in_sizes[0] / CH;   // 100000
    int E = in_sizes[1] / 2;    // 1600000

    int prep_threads = N * 64;
    if (prep_threads < E) prep_threads = E;

    k_prep_count<<<(prep_threads + 255) / 256, 256>>>((const float2*)x,
                                                      (const float2*)W, ei, E, N);
    k_alloc     <<<(N + 255) / 256, 256>>>(N);
    k_fill      <<<(E + 255) / 256, 256>>>(ei, E, N);
    k_aggregate <<<(N * 32 + 255) / 256, 256>>>(N);
    k_gemm      <<<(N + 127) / 128, 256>>>(bias, out, N);
}

// round 10
// speedup vs baseline: 1.0604x; 1.0604x over previous
#include <cuda_runtime.h>
#include <cuda_fp16.h>
#include <mma.h>
#include <stdint.h>

using namespace nvcuda;

#define N_NODES_MAX 100000
#define N_PAD       100096            // multiple of 128
#define E_MAX       1600000
#define CH          128

// ---------------- scratch (static device globals; zero-initialized) ----------
__device__ __align__(16) int     g_cnt[N_NODES_MAX];   // zero at start of each run
__device__ __align__(16) int     g_rowstart[N_NODES_MAX];
__device__ __align__(16) int     g_cursor[N_NODES_MAX];
__device__ __align__(16) int     g_csr_src[E_MAX];     // src only (weight folded into y)
__device__ __align__(16) float   g_dinv[N_NODES_MAX];
__device__               int     g_total;
__device__ __align__(16) __half2 g_yh[(size_t)N_NODES_MAX * 64];  // y = dinv*x (fp16)
__device__ __align__(16) __half2 g_aggh[(size_t)N_PAD * 64];      // agg in fp16
__device__ __align__(16) __half2 g_Wh[CH * CH / 2];               // W in fp16

// ---------------- kernel 1: count in-degree + convert W -----------------------
// relies on g_cnt == 0 (.bss run 1; re-zeroed by k_gemm each run).
__global__ void k_count(const float2* __restrict__ W2,
                        const int* __restrict__ ei, int E, int n) {
    int i = blockIdx.x * blockDim.x + threadIdx.x;
    if (i < CH * CH / 2) g_Wh[i] = __float22half2_rn(W2[i]);
    if (i < E) {
        unsigned dst = (unsigned)ei[E + i];
        if (dst < (unsigned)n) atomicAdd(&g_cnt[dst], 1);
    }
    if (i == 0) g_total = 0;
}

// ---------------- kernel 2: allocate CSR ranges (warp-aggregated atomic) ------
__global__ void k_alloc(int n) {
    int i    = blockIdx.x * blockDim.x + threadIdx.x;
    int lane = threadIdx.x & 31;
    int c = (i < n) ? g_cnt[i] : 0;

    int pre = c;
    #pragma unroll
    for (int off = 1; off < 32; off <<= 1) {
        int t = __shfl_up_sync(0xffffffffu, pre, off);
        if (lane >= off) pre += t;
    }
    int base = 0;
    if (lane == 31) base = atomicAdd(&g_total, pre);
    base = __shfl_sync(0xffffffffu, base, 31);
    if (i < n) {
        int rs = base + pre - c;
        g_rowstart[i] = rs;
        g_cursor[i]   = rs;
        g_dinv[i]     = rsqrtf(1.0f + (float)c);   // +1 self loop
    }
}

// ---------------- kernel 3: y = dinv[node] * x  (fp16 table) ------------------
__global__ void k_conv(const float2* __restrict__ x2, int n) {
    int i = blockIdx.x * blockDim.x + threadIdx.x;
    if (i < n * 64) {
        int node = i >> 6;
        float di = g_dinv[node];          // broadcast within 64-elem run
        float2 v = x2[i];
        g_yh[i] = __floats2half2_rn(v.x * di, v.y * di);
    }
}

// ---------------- kernel 4: CSR fill (src only, 4 B per edge) ------------------
__global__ void k_fill(const int* __restrict__ ei, int E, int n) {
    int e = blockIdx.x * blockDim.x + threadIdx.x;
    if (e < E) {
        unsigned src = (unsigned)ei[e];
        unsigned dst = (unsigned)ei[E + e];
        if (src < (unsigned)n && dst < (unsigned)n) {
            int pos = atomicAdd(&g_cursor[dst], 1);
            if ((unsigned)pos < (unsigned)E_MAX)
                g_csr_src[pos] = (int)src;
        }
    }
}

// ---------------- kernel 5: gather-aggregate (weight-free sum) -----------------
// agg[d] = di * ( y[d] + sum_{s in N(d)} y[s] )
// fp16 chunked accumulation (8 edges) into fp32 master accumulators.
__global__ void __launch_bounds__(256)
k_aggregate(int n) {
    const unsigned FULL = 0xffffffffu;
    int node = (blockIdx.x * blockDim.x + threadIdx.x) >> 5;
    int lane = threadIdx.x & 31;
    if (node >= n) return;

    float di = g_dinv[node];

    // seed: y[d]
    uint2 sv = ((const uint2*)(g_yh + (size_t)node * 64))[lane];
    float2 f0 = __half22float2(*(__half2*)&sv.x);
    float2 f1 = __half22float2(*(__half2*)&sv.y);
    float4 acc = make_float4(f0.x, f0.y, f1.x, f1.y);

    int start = g_rowstart[node];
    int end   = g_cursor[node];          // == rowstart + deg after fill
    int p0 = start;

    // full 32-edge groups: 4 chunks of 8 edges in fp16, flush to fp32
    for (; p0 + 32 <= end; p0 += 32) {
        int s = g_csr_src[p0 + lane];    // coalesced LDG.32
        #pragma unroll
        for (int jc = 0; jc < 4; jc++) {
            __half2 h0 = __float2half2_rn(0.0f);
            __half2 h1 = __float2half2_rn(0.0f);
            #pragma unroll
            for (int j = 0; j < 8; j++) {
                int sj = __shfl_sync(FULL, s, jc * 8 + j);
                uint2 v = ((const uint2*)(g_yh + (size_t)sj * 64))[lane];
                h0 = __hadd2(h0, *(__half2*)&v.x);
                h1 = __hadd2(h1, *(__half2*)&v.y);
            }
            float2 a = __half22float2(h0);
            float2 b = __half22float2(h1);
            acc.x += a.x; acc.y += a.y;
            acc.z += b.x; acc.w += b.y;
        }
    }
    // tail group (0..31 edges)
    if (p0 < end) {
        int cnt = end - p0;
        int s = (p0 + lane < end) ? g_csr_src[p0 + lane] : 0;
        __half2 h0 = __float2half2_rn(0.0f);
        __half2 h1 = __float2half2_rn(0.0f);
        int j = 0;
        for (; j < cnt; j++) {
            int sj = __shfl_sync(FULL, s, j);
            uint2 v = ((const uint2*)(g_yh + (size_t)sj * 64))[lane];
            h0 = __hadd2(h0, *(__half2*)&v.x);
            h1 = __hadd2(h1, *(__half2*)&v.y);
            if ((j & 7) == 7) {          // flush every 8 for precision
                float2 a = __half22float2(h0);
                float2 b = __half22float2(h1);
                acc.x += a.x; acc.y += a.y;
                acc.z += b.x; acc.w += b.y;
                h0 = __float2half2_rn(0.0f);
                h1 = __float2half2_rn(0.0f);
            }
        }
        float2 a = __half22float2(h0);
        float2 b = __half22float2(h1);
        acc.x += a.x; acc.y += a.y;
        acc.z += b.x; acc.w += b.y;
    }

    // final scale by di, store fp16
    __half2 o0 = __floats2half2_rn(acc.x * di, acc.y * di);
    __half2 o1 = __floats2half2_rn(acc.z * di, acc.w * di);
    uint2 ov = make_uint2(*(unsigned*)&o0, *(unsigned*)&o1);
    ((uint2*)(g_aggh + (size_t)node * 64))[lane] = ov;
}

// ---------------- kernel 6: HMMA GEMM  out = agg_h @ W_h + bias ---------------
__global__ void __launch_bounds__(256)
k_gemm(const float* __restrict__ bias, float* __restrict__ C, int M) {
    __shared__ __align__(16) __half As[128 * 136];
    __shared__ float Es[8 * 256];

    const int tid  = threadIdx.x;
    const int wid  = tid >> 5;
    const int lane = tid & 31;
    const int row0 = blockIdx.x * 128;
    const int warp_m = wid & 1;
    const int warp_n = wid >> 1;

    {
        const uint4* Ag  = (const uint4*)(g_aggh + (size_t)row0 * 64);
        uint4*       As4 = (uint4*)As;
        #pragma unroll
        for (int i = 0; i < 8; i++) {
            int idx = i * 256 + tid;
            int r   = idx >> 4;
            int c   = idx & 15;
            As4[r * 17 + c] = Ag[idx];
        }
    }
    __syncthreads();

    wmma::fragment<wmma::accumulator, 16, 16, 16, float> acc[4][2];
    #pragma unroll
    for (int mf = 0; mf < 4; mf++)
        #pragma unroll
        for (int nf = 0; nf < 2; nf++)
            wmma::fill_fragment(acc[mf][nf], 0.0f);

    const __half* Wh = (const __half*)g_Wh;

    #pragma unroll
    for (int k0 = 0; k0 < 128; k0 += 16) {
        wmma::fragment<wmma::matrix_a, 16, 16, 16, __half, wmma::row_major> af[4];
        #pragma unroll
        for (int mf = 0; mf < 4; mf++)
            wmma::load_matrix_sync(af[mf],
                As + (warp_m * 64 + mf * 16) * 136 + k0, 136);
        #pragma unroll
        for (int nf = 0; nf < 2; nf++) {
            wmma::fragment<wmma::matrix_b, 16, 16, 16, __half, wmma::row_major> bf;
            wmma::load_matrix_sync(bf, Wh + k0 * CH + warp_n * 32 + nf * 16, CH);
            #pragma unroll
            for (int mf = 0; mf < 4; mf++)
                wmma::mma_sync(acc[mf][nf], af[mf], bf, acc[mf][nf]);
        }
    }

    float* es = Es + wid * 256;
    #pragma unroll
    for (int mf = 0; mf < 4; mf++) {
        #pragma unroll
        for (int nf = 0; nf < 2; nf++) {
            wmma::store_matrix_sync(es, acc[mf][nf], 16, wmma::mem_row_major);
            __syncwarp();
            int r_in = lane >> 1;
            int c0   = (lane & 1) * 8;
            int gr   = row0 + warp_m * 64 + mf * 16 + r_in;
            int gc   = warp_n * 32 + nf * 16 + c0;
            if (gr < M) {
                float4 b0 = *(const float4*)(bias + gc);
                float4 b1 = *(const float4*)(bias + gc + 4);
                const float* p = es + r_in * 16 + c0;
                float4 o0 = make_float4(p[0] + b0.x, p[1] + b0.y,
                                        p[2] + b0.z, p[3] + b0.w);
                float4 o1 = make_float4(p[4] + b1.x, p[5] + b1.y,
                                        p[6] + b1.z, p[7] + b1.w);
                *(float4*)(C + (size_t)gr * CH + gc)     = o0;
                *(float4*)(C + (size_t)gr * CH + gc + 4) = o1;
            }
            __syncwarp();
        }
    }

    // restore invariant: g_cnt == 0 for next graph replay
    int gz = blockIdx.x * 256 + tid;
    if (gz < M) g_cnt[gz] = 0;
}

// ---------------- launch --------------------------------------------------------
extern "C" void kernel_launch(void* const* d_in, const int* in_sizes, int n_in,
                              void* d_out, int out_size) {
    const float* x    = (const float*)d_in[0];
    const int*   ei   = (const int*)d_in[1];     // int32 [2, E]
    const float* W    = (const float*)d_in[2];
    const float* bias = (const float*)d_in[3];
    float*       out  = (float*)d_out;

    int N = in_sizes[0] / CH;   // 100000
    int E = in_sizes[1] / 2;    // 1600000

    k_count     <<<(E + 255) / 256, 256>>>((const float2*)W, ei, E, N);
    k_alloc     <<<(N + 255) / 256, 256>>>(N);
    k_conv      <<<(N * 64 + 255) / 256, 256>>>((const float2*)x, N);
    k_fill      <<<(E + 255) / 256, 256>>>(ei, E, N);
    k_aggregate <<<(N * 32 + 255) / 256, 256>>>(N);
    k_gemm      <<<(N + 127) / 128, 256>>>(bias, out, N);
}